// round 2
// baseline (speedup 1.0000x reference)
#include <cuda_runtime.h>
#include <math.h>

#define BB 256
#define QQ 300
#define GG 16
#define NT 128   // threads per Hungarian block

// ---------------- device scratch (no allocations allowed) ----------------
__device__ float  g_cost[BB * GG * QQ];   // cost[b][g][q], ~4.9 MB
__device__ double g_l1[BB];               // per-batch selected-cost sum
__device__ int    g_cnt[BB];              // per-batch nval

__constant__ float c_tw[32] = {
    1.17236407f, 1.0166286f, 1.19620973f, 0.5544405f, 0.63531401f, 0.51258428f,
    1.08866652f, 1.15795989f, 1.07389395f, 0.98728399f, 1.12754142f, 1.05953744f,
    1.16945323f, 1.15512349f, 1.02097204f, 1.15795989f, 1.07147279f, 0.50627649f,
    1.07147279f, 0.61697221f, 1.16367678f, 1.0231585f, 1.18416106f, 1.04329092f,
    1.10645159f, 1.18416106f, 1.15795989f, 1.16367678f, 0.73949534f, 0.78760821f,
    1.08617476f, 1.00805777f
};

// ---------------- kernel 1: cost matrix ----------------
__global__ void cost_kernel(const float* __restrict__ ph,
                            const float* __restrict__ pr,
                            const float* __restrict__ pt,
                            const int* __restrict__ iid,
                            const int* __restrict__ vid,
                            const int* __restrict__ tgt) {
    int b = blockIdx.x;
    int q = threadIdx.x;
    __shared__ int si[GG], sv[GG], st[GG];
    if (q < GG) {
        si[q] = iid[b * GG + q];
        sv[q] = vid[b * GG + q];
        st[q] = tgt[b * GG + q];
    }
    __syncthreads();
    if (q >= QQ) return;

    float h[9], r[13], t[2];
    const float* hp = ph + (size_t)(b * QQ + q) * 9;
    const float* rp = pr + (size_t)(b * QQ + q) * 13;
    const float* tp = pt + (size_t)(b * QQ + q) * 2;

    float mh = -INFINITY, mr = -INFINITY, mt = -INFINITY;
#pragma unroll
    for (int i = 0; i < 9; i++)  { h[i] = hp[i]; mh = fmaxf(mh, h[i]); }
#pragma unroll
    for (int i = 0; i < 13; i++) { r[i] = rp[i]; mr = fmaxf(mr, r[i]); }
#pragma unroll
    for (int i = 0; i < 2; i++)  { t[i] = tp[i]; mt = fmaxf(mt, t[i]); }

    float sh = 0.f, sr = 0.f, stt = 0.f;
#pragma unroll
    for (int i = 0; i < 9; i++)  sh  += expf(h[i] - mh);
#pragma unroll
    for (int i = 0; i < 13; i++) sr  += expf(r[i] - mr);
#pragma unroll
    for (int i = 0; i < 2; i++)  stt += expf(t[i] - mt);

    float lh = mh + logf(sh);
    float lr = mr + logf(sr);
    float lt = mt + logf(stt);

#pragma unroll
    for (int g = 0; g < GG; g++) {
        float c = (lh - h[si[g]]) + (lr - r[sv[g]]) + (lt - t[st[g]]);
        g_cost[(size_t)(b * GG + g) * QQ + q] = c;
    }
}

// ---------------- kernel 2: Hungarian (JV) per batch ----------------
__global__ __launch_bounds__(NT) void hungarian_kernel(const int* __restrict__ mask) {
    int b   = blockIdx.x;
    int tid = threadIdx.x;

    __shared__ double s_v[QQ + 1];
    __shared__ double s_minv[QQ + 1];
    __shared__ double s_u[GG + 1];
    __shared__ int    s_p[QQ + 1];
    __shared__ int    s_way[QQ + 1];
    __shared__ unsigned char s_used[QQ + 1];
    __shared__ double s_rval[NT];
    __shared__ int    s_ridx[NT];
    __shared__ int    s_j0, s_i0, s_break, s_nval;
    __shared__ double s_delta;

    if (tid == 0) {
        int nv = 0;
        for (int g = 0; g < GG; g++) nv += mask[b * GG + g];
        s_nval = nv;
    }
    for (int j = tid; j <= QQ; j += NT) { s_v[j] = 0.0; s_p[j] = 0; s_way[j] = 0; }
    if (tid <= GG) s_u[tid] = 0.0;
    __syncthreads();

    const int n = s_nval;
    const float* Cb = &g_cost[(size_t)b * GG * QQ];

    for (int i = 1; i <= n; i++) {
        if (tid == 0) { s_p[0] = i; s_j0 = 0; }
        for (int j = tid; j <= QQ; j += NT) { s_minv[j] = INFINITY; s_used[j] = 0; }
        __syncthreads();

        while (true) {
            if (tid == 0) {
                s_used[s_j0] = 1;
                s_i0 = s_p[s_j0];
            }
            __syncthreads();
            const int    i0   = s_i0;
            const int    j0   = s_j0;
            const double u_i0 = s_u[i0];
            const float* Crow = Cb + (size_t)(i0 - 1) * QQ;

            // update minv/way over free columns; track local argmin (lowest index wins ties)
            double best = INFINITY;
            int    bidx = QQ + 2;
            for (int j = tid + 1; j <= QQ; j += NT) {
                if (!s_used[j]) {
                    double cur = (double)Crow[j - 1] - u_i0 - s_v[j];
                    if (cur < s_minv[j]) { s_minv[j] = cur; s_way[j] = j0; }
                    double mv = s_minv[j];
                    if (mv < best) { best = mv; bidx = j; }   // j increasing per thread
                }
            }
            s_rval[tid] = best;
            s_ridx[tid] = bidx;
            __syncthreads();
            for (int s = NT / 2; s > 0; s >>= 1) {
                if (tid < s) {
                    double ov = s_rval[tid + s]; int oi = s_ridx[tid + s];
                    if (ov < s_rval[tid] || (ov == s_rval[tid] && oi < s_ridx[tid])) {
                        s_rval[tid] = ov; s_ridx[tid] = oi;
                    }
                }
                __syncthreads();
            }
            if (tid == 0) s_delta = s_rval[0];
            __syncthreads();
            const int    j1    = s_ridx[0];
            const double delta = s_delta;

            // apply potentials update
            for (int j = tid; j <= QQ; j += NT) {
                if (s_used[j]) {
                    s_u[s_p[j]] += delta;   // p[j] distinct across used j
                    s_v[j]      -= delta;
                } else {
                    s_minv[j]   -= delta;
                }
            }
            __syncthreads();
            if (tid == 0) {
                s_j0    = j1;
                s_break = (s_p[j1] == 0);
            }
            __syncthreads();
            if (s_break) break;
        }

        // augment along the alternating path (serial, tiny)
        if (tid == 0) {
            int j0 = s_j0;
            while (j0) {
                int j1 = s_way[j0];
                s_p[j0] = s_p[j1];
                j0 = j1;
            }
        }
        __syncthreads();
    }

    // sum selected costs (float32 sim values, like the reference)
    double local = 0.0;
    for (int j = tid + 1; j <= QQ; j += NT) {
        int pj = s_p[j];
        if (pj > 0) local += (double)Cb[(size_t)(pj - 1) * QQ + (j - 1)];
    }
    s_rval[tid] = local;
    __syncthreads();
    for (int s = NT / 2; s > 0; s >>= 1) {
        if (tid < s) s_rval[tid] += s_rval[tid + s];
        __syncthreads();
    }
    if (tid == 0) { g_l1[b] = s_rval[0]; g_cnt[b] = n; }
}

// ---------------- kernel 3: BCE + final combine ----------------
__global__ void final_kernel(const float* __restrict__ IVT,
                             const int* __restrict__ triplet,
                             float* __restrict__ out) {
    const int tid = threadIdx.x;
    __shared__ double r1[256], r2[256], r3[256];

    double l1 = 0.0, cnt = 0.0;
    for (int b = tid; b < BB; b += 256) { l1 += g_l1[b]; cnt += (double)g_cnt[b]; }

    double bce = 0.0;
    for (int i = tid; i < BB * 32; i += 256) {
        float x = IVT[i];
        float t = (float)triplet[i];
        float v = fmaxf(x, 0.f) - x * t + log1pf(expf(-fabsf(x)));
        bce += (double)(c_tw[i & 31] * v);
    }
    r1[tid] = l1; r2[tid] = cnt; r3[tid] = bce;
    __syncthreads();
    for (int s = 128; s > 0; s >>= 1) {
        if (tid < s) { r1[tid] += r1[tid + s]; r2[tid] += r2[tid + s]; r3[tid] += r3[tid + s]; }
        __syncthreads();
    }
    if (tid == 0) {
        double loss1 = r1[0] / r2[0];
        double loss5 = r3[0] / (double)(BB * 32);
        out[0] = (float)(0.1 * loss1 + 1.0 * loss5);
    }
}

// ---------------- launch ----------------
extern "C" void kernel_launch(void* const* d_in, const int* in_sizes, int n_in,
                              void* d_out, int out_size) {
    const float* pred_head = (const float*)d_in[0];
    const float* pred_rel  = (const float*)d_in[1];
    const float* pred_tail = (const float*)d_in[2];
    const float* IVT       = (const float*)d_in[3];
    const int*   iid       = (const int*)d_in[4];
    const int*   vid       = (const int*)d_in[5];
    const int*   tgt       = (const int*)d_in[6];
    // d_in[7..9] (instrument, verb, target) unused by the reference
    const int*   triplet   = (const int*)d_in[10];
    const int*   mask      = (const int*)d_in[11];
    float* out = (float*)d_out;

    cost_kernel<<<BB, 320>>>(pred_head, pred_rel, pred_tail, iid, vid, tgt);
    hungarian_kernel<<<BB, NT>>>(mask);
    final_kernel<<<1, 256>>>(IVT, triplet, out);
}

// round 3
// speedup vs baseline: 2.0898x; 2.0898x over previous
#include <cuda_runtime.h>
#include <math.h>

#define BB 256
#define QQ 300
#define GG 16
#define KMAX 10   // ceil(QQ/32) columns per lane

// ---------------- device scratch (no allocations allowed) ----------------
__device__ double g_l1[BB];               // per-batch selected-cost sum
__device__ int    g_cnt[BB];              // per-batch nval

__constant__ float c_tw[32] = {
    1.17236407f, 1.0166286f, 1.19620973f, 0.5544405f, 0.63531401f, 0.51258428f,
    1.08866652f, 1.15795989f, 1.07389395f, 0.98728399f, 1.12754142f, 1.05953744f,
    1.16945323f, 1.15512349f, 1.02097204f, 1.15795989f, 1.07147279f, 0.50627649f,
    1.07147279f, 0.61697221f, 1.16367678f, 1.0231585f, 1.18416106f, 1.04329092f,
    1.10645159f, 1.18416106f, 1.15795989f, 1.16367678f, 0.73949534f, 0.78760821f,
    1.08617476f, 1.00805777f
};

// ---------------- fused kernel: cost tile (all 4 warps) + Hungarian (warp 0) ----
__global__ __launch_bounds__(128) void fused_kernel(
    const float* __restrict__ ph,
    const float* __restrict__ pr,
    const float* __restrict__ pt,
    const int* __restrict__ iid,
    const int* __restrict__ vid,
    const int* __restrict__ tgt,
    const int* __restrict__ mask)
{
    const int b   = blockIdx.x;
    const int tid = threadIdx.x;

    __shared__ float C[GG][QQ];           // cost[g][q], row-contiguous in q
    __shared__ float s_u[GG + 1];
    __shared__ int   s_p[QQ + 1];
    __shared__ int   s_way[QQ + 1];
    __shared__ int   si[GG], sv[GG], st[GG];

    if (tid < GG) {
        si[tid] = iid[b * GG + tid];
        sv[tid] = vid[b * GG + tid];
        st[tid] = tgt[b * GG + tid];
    }
    for (int j = tid; j <= QQ; j += 128) { s_p[j] = 0; s_way[j] = 0; }
    if (tid <= GG) s_u[tid] = 0.f;
    __syncthreads();

    // ---- phase 1: cost matrix into shared ----
    for (int q = tid; q < QQ; q += 128) {
        float h[9], r[13], t[2];
        const float* hp = ph + (size_t)(b * QQ + q) * 9;
        const float* rp = pr + (size_t)(b * QQ + q) * 13;
        const float* tp = pt + (size_t)(b * QQ + q) * 2;

        float mh = -INFINITY, mr = -INFINITY, mt = -INFINITY;
#pragma unroll
        for (int i = 0; i < 9; i++)  { h[i] = hp[i]; mh = fmaxf(mh, h[i]); }
#pragma unroll
        for (int i = 0; i < 13; i++) { r[i] = rp[i]; mr = fmaxf(mr, r[i]); }
#pragma unroll
        for (int i = 0; i < 2; i++)  { t[i] = tp[i]; mt = fmaxf(mt, t[i]); }

        float sh = 0.f, sr = 0.f, stt = 0.f;
#pragma unroll
        for (int i = 0; i < 9; i++)  sh  += expf(h[i] - mh);
#pragma unroll
        for (int i = 0; i < 13; i++) sr  += expf(r[i] - mr);
#pragma unroll
        for (int i = 0; i < 2; i++)  stt += expf(t[i] - mt);

        float lh = mh + logf(sh);
        float lr = mr + logf(sr);
        float lt = mt + logf(stt);

#pragma unroll
        for (int g = 0; g < GG; g++) {
            C[g][q] = (lh - h[si[g]]) + (lr - r[sv[g]]) + (lt - t[st[g]]);
        }
    }
    __syncthreads();

    // ---- phase 2: warp 0 runs JV Hungarian ----
    if (tid >= 32) return;
    const int lane = tid;

    unsigned mb = __ballot_sync(0xffffffffu, lane < GG && mask[b * GG + lane] != 0);
    const int n = __popc(mb);

    float v[KMAX], minv[KMAX];
#pragma unroll
    for (int k = 0; k < KMAX; k++) v[k] = 0.f;

    for (int i = 1; i <= n; i++) {
#pragma unroll
        for (int k = 0; k < KMAX; k++) minv[k] = INFINITY;
        unsigned used = 0;
        int j0 = 0;
        if (lane == 0) s_p[0] = i;
        __syncwarp();

        while (true) {
            // mark j0 used (lane that owns it sets its bit); column 0 handled by the
            // unconditional u[i] += delta below (p[0] == i while this row searches).
            if (j0 > 0 && (((j0 - 1) & 31) == lane))
                used |= 1u << ((j0 - 1) >> 5);

            const int   i0   = s_p[j0];
            const float u_i0 = s_u[i0];
            const float* Crow = &C[i0 - 1][0];

            float best = INFINITY;
            int   bidx = QQ + 2;
#pragma unroll
            for (int k = 0; k < KMAX; k++) {
                int j = 1 + lane + 32 * k;
                if (j <= QQ && !((used >> k) & 1u)) {
                    float cur = Crow[j - 1] - u_i0 - v[k];
                    if (cur < minv[k]) { minv[k] = cur; s_way[j] = j0; }
                    if (minv[k] < best) { best = minv[k]; bidx = j; }  // k ascending => lowest j wins ties
                }
            }
            // warp argmin, lowest index wins ties (matches np.argmin)
#pragma unroll
            for (int off = 16; off > 0; off >>= 1) {
                float ov = __shfl_down_sync(0xffffffffu, best, off);
                int   oi = __shfl_down_sync(0xffffffffu, bidx, off);
                if (ov < best || (ov == best && oi < bidx)) { best = ov; bidx = oi; }
            }
            const float delta = __shfl_sync(0xffffffffu, best, 0);
            const int   j1    = __shfl_sync(0xffffffffu, bidx, 0);

            // potentials update
#pragma unroll
            for (int k = 0; k < KMAX; k++) {
                int j = 1 + lane + 32 * k;
                if (j <= QQ) {
                    if ((used >> k) & 1u) {
                        v[k] -= delta;
                        s_u[s_p[j]] += delta;     // distinct p[j] across used cols
                    } else {
                        minv[k] -= delta;
                    }
                }
            }
            if (lane == 0) s_u[i] += delta;       // virtual column 0 (p[0] = i)
            __syncwarp();

            if (s_p[j1] == 0) { j0 = j1; break; }
            j0 = j1;
        }

        // augment alternating path (serial, tiny)
        if (lane == 0) {
            int jj = j0;
            while (jj) {
                int jp = s_way[jj];
                s_p[jj] = s_p[jp];
                jj = jp;
            }
        }
        __syncwarp();
    }

    // sum selected float32 costs
    double local = 0.0;
#pragma unroll
    for (int k = 0; k < KMAX; k++) {
        int j = 1 + lane + 32 * k;
        if (j <= QQ) {
            int pj = s_p[j];
            if (pj > 0) local += (double)C[pj - 1][j - 1];
        }
    }
#pragma unroll
    for (int off = 16; off > 0; off >>= 1)
        local += __shfl_down_sync(0xffffffffu, local, off);
    if (lane == 0) { g_l1[b] = local; g_cnt[b] = n; }
}

// ---------------- kernel 2: BCE + final combine ----------------
__global__ void final_kernel(const float* __restrict__ IVT,
                             const int* __restrict__ triplet,
                             float* __restrict__ out) {
    const int tid = threadIdx.x;
    __shared__ double r1[256], r2[256], r3[256];

    double l1 = 0.0, cnt = 0.0;
    for (int b = tid; b < BB; b += 256) { l1 += g_l1[b]; cnt += (double)g_cnt[b]; }

    double bce = 0.0;
    for (int i = tid; i < BB * 32; i += 256) {
        float x = IVT[i];
        float t = (float)triplet[i];
        float v = fmaxf(x, 0.f) - x * t + log1pf(expf(-fabsf(x)));
        bce += (double)(c_tw[i & 31] * v);
    }
    r1[tid] = l1; r2[tid] = cnt; r3[tid] = bce;
    __syncthreads();
    for (int s = 128; s > 0; s >>= 1) {
        if (tid < s) { r1[tid] += r1[tid + s]; r2[tid] += r2[tid + s]; r3[tid] += r3[tid + s]; }
        __syncthreads();
    }
    if (tid == 0) {
        double loss1 = r1[0] / r2[0];
        double loss5 = r3[0] / (double)(BB * 32);
        out[0] = (float)(0.1 * loss1 + 1.0 * loss5);
    }
}

// ---------------- launch ----------------
extern "C" void kernel_launch(void* const* d_in, const int* in_sizes, int n_in,
                              void* d_out, int out_size) {
    const float* pred_head = (const float*)d_in[0];
    const float* pred_rel  = (const float*)d_in[1];
    const float* pred_tail = (const float*)d_in[2];
    const float* IVT       = (const float*)d_in[3];
    const int*   iid       = (const int*)d_in[4];
    const int*   vid       = (const int*)d_in[5];
    const int*   tgt       = (const int*)d_in[6];
    // d_in[7..9] (instrument, verb, target) unused by the reference
    const int*   triplet   = (const int*)d_in[10];
    const int*   mask      = (const int*)d_in[11];
    float* out = (float*)d_out;

    fused_kernel<<<BB, 128>>>(pred_head, pred_rel, pred_tail, iid, vid, tgt, mask);
    final_kernel<<<1, 256>>>(IVT, triplet, out);
}